// round 16
// baseline (speedup 1.0000x reference)
#include <cuda_runtime.h>
#include <cuda_bf16.h>

#define BB   32
#define TT   1024
#define DD   512
#define HH   512
#define G4   2048
#define NCTA 128

// ---------------- scratch (static device globals; no allocs allowed) --------
__device__ float    g_xw[(size_t)TT * BB * G4];   // [t][b][4H] precomputed x@Wx + bias
__device__ __nv_bfloat16 g_hhi[2][BB * HH];       // hidden state split-high, [b][j]
__device__ __nv_bfloat16 g_hlo[2][BB * HH];       // hidden state split-low
__device__ unsigned g_bars[2048];                 // 8 barrier counters, 1KB apart (c*256)
__device__ unsigned g_flag;                       // barrier epoch flag
__device__ __nv_bfloat16 g_xhi[(size_t)TT * BB * DD];  // X split-high, [m][k]
__device__ __nv_bfloat16 g_xlo[(size_t)TT * BB * DD];  // X split-low
__device__ __nv_bfloat16 g_whiT[(size_t)G4 * DD];      // Wx^T split-high, [n][k]
__device__ __nv_bfloat16 g_wloT[(size_t)G4 * DD];      // Wx^T split-low

__device__ __forceinline__ float fsig(float x) {
    return 1.f / (1.f + __expf(-x));
}
__device__ __forceinline__ float ftanh(float x) {
    float ax = fminf(fabsf(x), 15.f);
    float e  = __expf(2.f * ax);
    float r  = (e - 1.f) / (e + 1.f);
    return copysignf(r, x);
}

// ---------------- tensor-core helpers ----------------------------------------
__device__ __forceinline__ void ldm4(unsigned* r, unsigned addr) {
    asm volatile("ldmatrix.sync.aligned.m8n8.x4.shared.b16 {%0,%1,%2,%3}, [%4];"
                 : "=r"(r[0]), "=r"(r[1]), "=r"(r[2]), "=r"(r[3]) : "r"(addr));
}
__device__ __forceinline__ void mma_bf16(float* c, const unsigned* a, const unsigned* b) {
    asm volatile(
        "mma.sync.aligned.m16n8k16.row.col.f32.bf16.bf16.f32 "
        "{%0,%1,%2,%3}, {%4,%5,%6,%7}, {%8,%9}, {%0,%1,%2,%3};"
        : "+f"(c[0]), "+f"(c[1]), "+f"(c[2]), "+f"(c[3])
        : "r"(a[0]), "r"(a[1]), "r"(a[2]), "r"(a[3]), "r"(b[0]), "r"(b[1]));
}

// ---------------- reset: barrier counters + flag + h buffer 0 ----------------
__global__ void reset_kernel() {
    int idx = blockIdx.x * blockDim.x + threadIdx.x;
    if (idx < 2048) g_bars[idx] = 0u;
    if (idx == 0)   g_flag = 0u;
    if (idx < (BB * HH) / 2) {
        ((unsigned*)g_hhi)[idx] = 0u;     // buffer 0 of both splits
        ((unsigned*)g_hlo)[idx] = 0u;
    }
}

// ---------------- conversion: X and Wx splits in one kernel ------------------
__global__ void conv_all_kernel(const float* __restrict__ X, const float* __restrict__ Wx) {
    if (blockIdx.x < 16384) {
        size_t i = ((size_t)blockIdx.x * 256 + threadIdx.x) * 4;
        if (i >= (size_t)TT * BB * DD) return;
        float4 v = *(const float4*)(X + i);
        __nv_bfloat16 h[4], l[4];
        float vv[4] = {v.x, v.y, v.z, v.w};
#pragma unroll
        for (int q = 0; q < 4; q++) {
            h[q] = __float2bfloat16(vv[q]);
            l[q] = __float2bfloat16(vv[q] - __bfloat162float(h[q]));
        }
        *(uint2*)(g_xhi + i) = *(uint2*)h;
        *(uint2*)(g_xlo + i) = *(uint2*)l;
    } else {
        int idx = (blockIdx.x - 16384) * 256 + threadIdx.x;
        if (idx >= DD * G4) return;
        int k = idx >> 11, n = idx & (G4 - 1);
        float w = Wx[idx];
        __nv_bfloat16 hi = __float2bfloat16(w);
        __nv_bfloat16 lo = __float2bfloat16(w - __bfloat162float(hi));
        g_whiT[(size_t)n * DD + k] = hi;
        g_wloT[(size_t)n * DD + k] = lo;
    }
}

// ---------------- kernel 1: XW via bf16-split tensor cores (validated) -------
#define XW_STAGE 24576
#define XW_ROWP  48
__global__ __launch_bounds__(256) void gemm_xw_tc_kernel(const float* __restrict__ bias) {
    extern __shared__ char xsmem[];
    unsigned sbase = (unsigned)__cvta_generic_to_shared(xsmem);

    int tid  = threadIdx.x;
    int lane = tid & 31;
    int w    = tid >> 5;
    int wm   = w >> 1, wn = w & 1;
    int m0   = blockIdx.y * 128;
    int n0   = blockIdx.x * 128;
    int g    = lane >> 2, tig = lane & 3;

    const __nv_bfloat16* srcs[4] = {
        g_xhi + (size_t)m0 * DD, g_xlo + (size_t)m0 * DD,
        g_whiT + (size_t)n0 * DD, g_wloT + (size_t)n0 * DD };

    float acc[2][8][4];
#pragma unroll
    for (int mt = 0; mt < 2; mt++)
#pragma unroll
        for (int f = 0; f < 8; f++)
#pragma unroll
            for (int q = 0; q < 4; q++) acc[mt][f][q] = 0.f;

    auto load_stage = [&](int s, int kk) {
#pragma unroll
        for (int it = 0; it < 2; it++) {
            int task = tid + 256 * it;
            int arr  = task >> 7, row = task & 127;
            const __nv_bfloat16* src = srcs[arr] + (size_t)row * DD + kk;
            unsigned dst = sbase + (s & 1) * XW_STAGE + arr * 6144 + row * XW_ROWP;
            asm volatile("cp.async.cg.shared.global [%0], [%1], 16;"
                         :: "r"(dst), "l"(src) : "memory");
            asm volatile("cp.async.cg.shared.global [%0], [%1], 16;"
                         :: "r"(dst + 16), "l"(src + 8) : "memory");
        }
        asm volatile("cp.async.commit_group;");
    };

    load_stage(0, 0);

    int a_row_off = ((lane >> 3) & 1) * 8 + (lane & 7);
    int a_k_off   = ((lane >> 4) & 1) * 16;
    int b_row_off = ((lane >> 4) & 1) * 8 + (lane & 7);
    int b_k_off   = ((lane >> 3) & 1) * 16;

    for (int s = 0; s < 32; s++) {
        if (s + 1 < 32) load_stage(s + 1, (s + 1) * 16);
        if (s + 1 < 32) { asm volatile("cp.async.wait_group 1;" ::: "memory"); }
        else            { asm volatile("cp.async.wait_group 0;" ::: "memory"); }
        __syncthreads();

        unsigned st = sbase + (s & 1) * XW_STAGE;
        unsigned ah[2][4], al[2][4], bh[8][2], bl8[8][2];
#pragma unroll
        for (int mt = 0; mt < 2; mt++) {
            unsigned rowb = (wm * 32 + mt * 16 + a_row_off) * XW_ROWP + a_k_off;
            ldm4(ah[mt], st + 0    + rowb);
            ldm4(al[mt], st + 6144 + rowb);
        }
#pragma unroll
        for (int fp = 0; fp < 4; fp++) {
            unsigned rowb = (wn * 64 + fp * 16 + b_row_off) * XW_ROWP + b_k_off;
            unsigned r4[4];
            ldm4(r4, st + 12288 + rowb);
            bh[fp * 2][0] = r4[0];  bh[fp * 2][1] = r4[1];
            bh[fp * 2 + 1][0] = r4[2];  bh[fp * 2 + 1][1] = r4[3];
            ldm4(r4, st + 18432 + rowb);
            bl8[fp * 2][0] = r4[0];  bl8[fp * 2][1] = r4[1];
            bl8[fp * 2 + 1][0] = r4[2];  bl8[fp * 2 + 1][1] = r4[3];
        }
#pragma unroll
        for (int mt = 0; mt < 2; mt++)
#pragma unroll
            for (int f = 0; f < 8; f++) {
                mma_bf16(acc[mt][f], ah[mt], bh[f]);
                mma_bf16(acc[mt][f], ah[mt], bl8[f]);
                mma_bf16(acc[mt][f], al[mt], bh[f]);
            }
        __syncthreads();
    }

#pragma unroll
    for (int f = 0; f < 8; f++) {
        int col = n0 + wn * 64 + f * 8 + tig * 2;
        float bl0 = bias[col], bl1 = bias[col + 1];
#pragma unroll
        for (int mt = 0; mt < 2; mt++) {
            int mr0 = m0 + wm * 32 + mt * 16 + g;
            int bb = mr0 >> 10, t = mr0 & 1023;
            float2 v0 = {acc[mt][f][0] + bl0, acc[mt][f][1] + bl1};
            *(float2*)&g_xw[((size_t)t * BB + bb) * G4 + col] = v0;
            int mr1 = mr0 + 8;
            bb = mr1 >> 10; t = mr1 & 1023;
            float2 v1 = {acc[mt][f][2] + bl0, acc[mt][f][3] + bl1};
            *(float2*)&g_xw[((size_t)t * BB + bb) * G4 + col] = v1;
        }
    }
}

// ---------------- kernel 2: persistent recurrence, bf16-split TC GEMM --------
// Identical to R15 except the grid barrier: 8 distributed arrival counters
// (1KB apart -> distinct LTS slices; 16 serialized arrivals each instead of
// 128 on one address) + master CTA 0 combines and broadcasts an epoch flag.
#define WHP      520
#define OFF_WHHI 0
#define OFF_WHLO 16640
#define OFF_HHI  33280
#define OFF_HLO  66560
#define OFF_RED  99840
#define SMEM_REC 118272
__global__ __launch_bounds__(256, 1) void lstm_rec_kernel(
    const float* __restrict__ Wh, float* __restrict__ out)
{
    extern __shared__ char smem[];
    unsigned sb = (unsigned)__cvta_generic_to_shared(smem);
    __nv_bfloat16* whhi = (__nv_bfloat16*)(smem + OFF_WHHI);
    __nv_bfloat16* whlo = (__nv_bfloat16*)(smem + OFF_WHLO);
    float*         red_s = (float*)(smem + OFF_RED);   // [8][32][18]

    int tid = threadIdx.x;
    int j0  = blockIdx.x * 4;

    // split Wh slice into smem: row c = gate*4+jj (16 rows x 512 k)
    for (int idx = tid; idx < 16 * 512; idx += 256) {
        int k = idx >> 4, c = idx & 15;
        float wv = Wh[(size_t)k * G4 + (c >> 2) * HH + j0 + (c & 3)];
        __nv_bfloat16 hi = __float2bfloat16(wv);
        __nv_bfloat16 lo = __float2bfloat16(wv - __bfloat162float(hi));
        whhi[c * WHP + k] = hi;
        whlo[c * WHP + k] = lo;
    }

    int w    = tid >> 5;
    int lane = tid & 31;
    int g    = lane >> 2, tig = lane & 3;

    int a_row_off = ((lane >> 3) & 1) * 8 + (lane & 7);
    int a_k_off   = ((lane >> 4) & 1) * 16;
    int b_row_off = ((lane >> 4) & 1) * 8 + (lane & 7);
    int b_k_off   = ((lane >> 3) & 1) * 16;

    // update role (tid < 128): (batch ub, h-col j0+uj)
    int ub = tid >> 2, uj = tid & 3;
    float creg = 0.f;
    float* outp = out + ((size_t)ub * TT) * HH + j0 + uj;

    unsigned* my_bar = &g_bars[(blockIdx.x & 7) * 256];
    unsigned bar_goal16 = 16;     // per-counter cumulative target
    unsigned flag_val   = 1;      // epoch value

    __syncthreads();

    float px0 = 0.f, px1 = 0.f, px2 = 0.f, px3 = 0.f;
    if (tid < 128) {
        const float* xr = g_xw + (size_t)ub * G4 + j0 + uj;
        px0 = __ldg(xr);        px1 = __ldg(xr + 512);
        px2 = __ldg(xr + 1024); px3 = __ldg(xr + 1536);
    }

    for (int t = 0; t < TT; t++) {
        int buf = t & 1;
        // per-warp h load: k-slice [64w, 64w+64), both splits, 2 commit groups
        {
#pragma unroll
            for (int grp = 0; grp < 2; grp++) {
#pragma unroll
                for (int sp = 0; sp < 2; sp++) {
                    const __nv_bfloat16* gsrc = sp ? g_hlo[buf] : g_hhi[buf];
                    unsigned hb = sb + (sp ? OFF_HLO : OFF_HHI);
#pragma unroll
                    for (int i = 0; i < 4; i++) {
                        int v  = i * 32 + lane;          // 0..127
                        int r  = v >> 2, c4 = v & 3;
                        int ko = 64 * w + grp * 32 + c4 * 8;
                        asm volatile("cp.async.cg.shared.global [%0], [%1], 16;"
                                     :: "r"(hb + (unsigned)(r * 1040 + ko * 2)),
                                        "l"(gsrc + (size_t)r * HH + ko)
                                     : "memory");
                    }
                }
                asm volatile("cp.async.commit_group;");
            }
        }

        float acc[2][2][4];
#pragma unroll
        for (int mt = 0; mt < 2; mt++)
#pragma unroll
            for (int nt = 0; nt < 2; nt++)
#pragma unroll
                for (int q = 0; q < 4; q++) acc[mt][nt][q] = 0.f;

#pragma unroll
        for (int grp = 0; grp < 2; grp++) {
            if (grp == 0) { asm volatile("cp.async.wait_group 1;" ::: "memory"); }
            else          { asm volatile("cp.async.wait_group 0;" ::: "memory"); }
            __syncwarp();
#pragma unroll
            for (int ktl = 0; ktl < 2; ktl++) {
                int kb = 128 * w + grp * 64 + ktl * 32;   // byte offset of 16-k tile
                unsigned ahi[2][4], alo[2][4];
#pragma unroll
                for (int mt = 0; mt < 2; mt++) {
                    unsigned rowb = (mt * 16 + a_row_off) * 1040 + kb + a_k_off;
                    ldm4(ahi[mt], sb + OFF_HHI + rowb);
                    ldm4(alo[mt], sb + OFF_HLO + rowb);
                }
                unsigned r4[4], bh[2][2], bl[2][2];
                unsigned rowbB = b_row_off * 1040 + kb + b_k_off;
                ldm4(r4, sb + OFF_WHHI + rowbB);
                bh[0][0] = r4[0]; bh[0][1] = r4[1];
                bh[1][0] = r4[2]; bh[1][1] = r4[3];
                ldm4(r4, sb + OFF_WHLO + rowbB);
                bl[0][0] = r4[0]; bl[0][1] = r4[1];
                bl[1][0] = r4[2]; bl[1][1] = r4[3];
#pragma unroll
                for (int mt = 0; mt < 2; mt++)
#pragma unroll
                    for (int nt = 0; nt < 2; nt++) {
                        mma_bf16(acc[mt][nt], ahi[mt], bh[nt]);
                        mma_bf16(acc[mt][nt], ahi[mt], bl[nt]);
                        mma_bf16(acc[mt][nt], alo[mt], bh[nt]);
                        mma_bf16(acc[mt][nt], alo[mt], bl[nt]);
                    }
            }
        }

        // store warp partials: red_s[w][row=b][col=c], rows from C-fragment map
        {
            float* rw = red_s + w * 32 * 18;
#pragma unroll
            for (int mt = 0; mt < 2; mt++)
#pragma unroll
                for (int nt = 0; nt < 2; nt++) {
                    int col = nt * 8 + tig * 2;
                    float2 v0 = {acc[mt][nt][0], acc[mt][nt][1]};
                    float2 v1 = {acc[mt][nt][2], acc[mt][nt][3]};
                    *(float2*)&rw[(mt * 16 + g) * 18 + col]     = v0;
                    *(float2*)&rw[(mt * 16 + g + 8) * 18 + col] = v1;
                }
        }
        __syncthreads();

        // update threads: sum 8 warp partials, gates at cols uj, uj+4, uj+8, uj+12
        if (tid < 128) {
            float zi = 0.f, zf = 0.f, zg = 0.f, zo = 0.f;
#pragma unroll
            for (int w8 = 0; w8 < 8; w8++) {
                const float* r = red_s + (w8 * 32 + ub) * 18;
                zi += r[uj];      zf += r[4 + uj];
                zg += r[8 + uj];  zo += r[12 + uj];
            }
            zi += px0; zf += px1; zg += px2; zo += px3;
            float ig = fsig(zi);
            float fg = fsig(zf);
            float gg = ftanh(zg);
            float og = fsig(zo);
            float cn = fg * creg + ig * gg;
            creg = cn;
            float hn = og * ftanh(cn);
            __nv_bfloat16 hi = __float2bfloat16(hn);
            __nv_bfloat16 lo = __float2bfloat16(hn - __bfloat162float(hi));
            int nb = (t + 1) & 1;
            g_hhi[nb][(size_t)ub * HH + j0 + uj] = hi;
            g_hlo[nb][(size_t)ub * HH + j0 + uj] = lo;
            outp[(size_t)t * HH] = hn;

            // prefetch next step's px under the barrier
            int tn = (t + 1 < TT) ? t + 1 : t;
            const float* xr = g_xw + ((size_t)tn * BB + ub) * G4 + j0 + uj;
            px0 = __ldg(xr);        px1 = __ldg(xr + 512);
            px2 = __ldg(xr + 1024); px3 = __ldg(xr + 1536);
        }
        __syncthreads();

        // distributed two-level grid barrier
        if (tid == 0) {
            asm volatile("red.release.gpu.global.add.u32 [%0], %1;"
                         :: "l"(my_bar), "r"(1u) : "memory");
            if (blockIdx.x == 0) {
                // master: wait for all 8 counters, then publish epoch flag
#pragma unroll
                for (int c = 0; c < 8; c++) {
                    unsigned v;
                    do {
                        asm volatile("ld.acquire.gpu.global.u32 %0, [%1];"
                                     : "=r"(v) : "l"(&g_bars[c * 256]) : "memory");
                    } while (v < bar_goal16);
                }
                asm volatile("st.release.gpu.global.u32 [%0], %1;"
                             :: "l"(&g_flag), "r"(flag_val) : "memory");
            } else {
                unsigned v;
                do {
                    asm volatile("ld.acquire.gpu.global.u32 %0, [%1];"
                                 : "=r"(v) : "l"(&g_flag) : "memory");
                } while (v < flag_val);
            }
        }
        bar_goal16 += 16;
        flag_val   += 1;
        __syncthreads();
    }
}

// ---------------- kernel 3: gather final states ------------------------------
__global__ void gather_final_kernel(const int* __restrict__ lenraw, float* __restrict__ out) {
    __shared__ int is32;
    if (threadIdx.x == 0) {
        const long long* l64 = (const long long*)lenraw;
        int bad = 0;
        for (int b = 0; b < 16; b++) {
            long long v = l64[b];
            if (v < 0 || v > (long long)TT) bad = 1;
        }
        is32 = bad;
    }
    __syncthreads();
    int idx = blockIdx.x * blockDim.x + threadIdx.x;
    if (idx >= BB * HH) return;
    int b = idx >> 9, j = idx & 511;
    long long len = is32 ? (long long)lenraw[b] : ((const long long*)lenraw)[b];
    long long tt = len > 0 ? len - 1 : 0;
    out[(size_t)BB * TT * HH + idx] = out[((size_t)b * TT + tt) * HH + j];
}

// ---------------- launch ------------------------------------------------------
extern "C" void kernel_launch(void* const* d_in, const int* in_sizes, int n_in,
                              void* d_out, int out_size) {
    const float* X    = (const float*)d_in[0];
    const int*   lenr = (const int*)  d_in[1];
    const float* Wx   = (const float*)d_in[2];
    const float* Wh   = (const float*)d_in[3];
    const float* bias = (const float*)d_in[4];
    float* out = (float*)d_out;

    int smem_xw = 2 * XW_STAGE;                              // 49,152 B

    cudaFuncSetAttribute(lstm_rec_kernel,
                         cudaFuncAttributeMaxDynamicSharedMemorySize, SMEM_REC);
    cudaFuncSetAttribute(lstm_rec_kernel,
                         cudaFuncAttributePreferredSharedMemoryCarveout, 100);
    cudaFuncSetAttribute(gemm_xw_tc_kernel,
                         cudaFuncAttributeMaxDynamicSharedMemorySize, smem_xw);

    reset_kernel<<<64, 256>>>();
    conv_all_kernel<<<20480, 256>>>(X, Wx);
    gemm_xw_tc_kernel<<<dim3(16, 256), 256, smem_xw>>>(bias);
    lstm_rec_kernel<<<NCTA, 256, SMEM_REC>>>(Wh, out);       // launch slot #4
    gather_final_kernel<<<64, 256>>>(lenr, out);
}